// round 2
// baseline (speedup 1.0000x reference)
#include <cuda_runtime.h>
#include <cuda_bf16.h>
#include <math.h>
#include <stdint.h>

// ----------------------------------------------------------------------------
// Problem constants
//   B=2, H=W=256, C=256, P0=P1=8, R0=R1=32, L=1024, NH=8, DH=32,
//   MID=1024, HD=16384, EPS=1e-5
// ----------------------------------------------------------------------------

#define DINLINE __device__ __forceinline__

// ---------------- scratch (device globals; no allocation allowed) -----------
__device__ __nv_bfloat16 g_yhd  [2048L * 16384];   // LN1 + unfold, bf16
__device__ __nv_bfloat16 g_y1   [2048L * 256];     // down-proj out
__device__ __nv_bfloat16 g_qkv  [2048L * 768];     // qkv
__device__ __nv_bfloat16 g_oattn[2048L * 256];     // attention out
__device__ __nv_bfloat16 g_oproj[2048L * 256];     // proj out
__device__ float         g_x2   [131072L * 256];   // x + folded up-proj (fp32)
__device__ __nv_bfloat16 g_ln2  [131072L * 256];   // LN2 out
__device__ __nv_bfloat16 g_h1   [131072L * 1024];  // fc1+gelu out
// bf16 weights (converted each call)
__device__ __nv_bfloat16 g_wdown[256L * 16384];
__device__ __nv_bfloat16 g_wup  [16384L * 256];
__device__ __nv_bfloat16 g_wqkv [768L * 256];
__device__ __nv_bfloat16 g_wproj[256L * 256];
__device__ __nv_bfloat16 g_wfc1 [1024L * 256];
__device__ __nv_bfloat16 g_wfc2 [256L * 1024];

// ---------------- fp32 -> bf16 convert ---------------------------------------
__global__ void cvt_bf16_kernel(const float* __restrict__ in,
                                __nv_bfloat16* __restrict__ out, int n) {
    int i = blockIdx.x * 256 + threadIdx.x;
    if (i < n) out[i] = __float2bfloat16(in[i]);
}

// ---------------- LayerNorm (optionally fused with the unfold permutation) ---
// Each warp handles one row of C=256. PERM=true writes into (B, L, HD) layout:
//   y_hd[b, r0*32+r1, (p0*8+p1)*256 + c] = LN(x[b, r0*8+p0, r1*8+p1, c])
template <bool PERM>
__global__ void ln_kernel(const float* __restrict__ in,
                          const float* __restrict__ gamma,
                          const float* __restrict__ beta,
                          __nv_bfloat16* __restrict__ out) {
    int row  = blockIdx.x * 8 + (threadIdx.x >> 5);
    int lane = threadIdx.x & 31;
    const float* p = in + (long)row * 256;

    float v[8];
    float s = 0.f;
#pragma unroll
    for (int i = 0; i < 8; i++) { v[i] = p[lane + i * 32]; s += v[i]; }
#pragma unroll
    for (int o = 16; o > 0; o >>= 1) s += __shfl_xor_sync(0xffffffffu, s, o);
    float mean = s * (1.f / 256.f);
    float q = 0.f;
#pragma unroll
    for (int i = 0; i < 8; i++) { float d = v[i] - mean; q += d * d; }
#pragma unroll
    for (int o = 16; o > 0; o >>= 1) q += __shfl_xor_sync(0xffffffffu, q, o);
    float rstd = rsqrtf(q * (1.f / 256.f) + 1e-5f);

    long obase;
    if (PERM) {
        int b  = row >> 16;
        int hh = (row >> 8) & 255;
        int ww = row & 255;
        int r0 = hh >> 3, p0 = hh & 7;
        int r1 = ww >> 3, p1 = ww & 7;
        long n = (long)b * 1024 + r0 * 32 + r1;
        obase = n * 16384 + (long)(p0 * 8 + p1) * 256;
    } else {
        obase = (long)row * 256;
    }
#pragma unroll
    for (int i = 0; i < 8; i++) {
        int c = lane + i * 32;
        float y = (v[i] - mean) * rstd * gamma[c] + beta[c];
        out[obase + c] = __float2bfloat16(y);
    }
}

// ---------------- generic NT bf16 GEMM (mma.sync m16n8k16, fp32 accum) -------
// C[M,N] = A[M,K] (row-major bf16) * B[N,K]^T (row-major bf16) + epilogue
// EPI: 0 = bf16(acc+bias)
//      1 = bf16(gelu(acc+bias))           (exact GELU via erff)
//      2 = fp32 scatter (fold): outf[dst] = res[dst] + acc + bias
//      3 = fp32 outf[idx]      = res[idx] + acc + bias
template <int BM, int BN, int WARPS_M, int WARPS_N, int EPI>
__global__ void __launch_bounds__(WARPS_M * WARPS_N * 32)
gemm_nt(const __nv_bfloat16* __restrict__ A,
        const __nv_bfloat16* __restrict__ B,
        int M, int N, int K,
        const float* __restrict__ bias,
        __nv_bfloat16* __restrict__ outb,
        float* __restrict__ outf,
        const float* __restrict__ res) {
    constexpr int BK      = 32;
    constexpr int THREADS = WARPS_M * WARPS_N * 32;
    constexpr int WM      = BM / WARPS_M;
    constexpr int WN      = BN / WARPS_N;
    constexpr int MM      = WM / 16;
    constexpr int MN      = WN / 8;
    constexpr int LDSB    = BK + 8;   // padded bf16 stride (80B rows, 16B aligned)
    static_assert(MN % 2 == 0, "");

    __shared__ __nv_bfloat16 smA[2][BM * LDSB];
    __shared__ __nv_bfloat16 smB[2][BN * LDSB];

    const int tid  = threadIdx.x;
    const int lane = tid & 31;
    const int wid  = tid >> 5;
    const int wm   = wid / WARPS_N;
    const int wn   = wid % WARPS_N;
    const int m0   = blockIdx.y * BM;
    const int n0   = blockIdx.x * BN;
    const int nk   = K / BK;

    auto ldA = [&](int st, int kt) {
#pragma unroll
        for (int it = 0; it < (BM * BK / 8) / THREADS; it++) {
            int c = tid + it * THREADS;
            int r = c >> 2, kc = (c & 3) << 3;
            const __nv_bfloat16* src = A + (long)(m0 + r) * K + kt + kc;
            uint32_t dst = (uint32_t)__cvta_generic_to_shared(&smA[st][r * LDSB + kc]);
            asm volatile("cp.async.cg.shared.global [%0], [%1], 16;\n" ::"r"(dst), "l"(src));
        }
    };
    auto ldB = [&](int st, int kt) {
#pragma unroll
        for (int it = 0; it < (BN * BK / 8) / THREADS; it++) {
            int c = tid + it * THREADS;
            int r = c >> 2, kc = (c & 3) << 3;
            const __nv_bfloat16* src = B + (long)(n0 + r) * K + kt + kc;
            uint32_t dst = (uint32_t)__cvta_generic_to_shared(&smB[st][r * LDSB + kc]);
            asm volatile("cp.async.cg.shared.global [%0], [%1], 16;\n" ::"r"(dst), "l"(src));
        }
    };

    ldA(0, 0);
    ldB(0, 0);
    asm volatile("cp.async.commit_group;\n");

    float acc[MM][MN][4] = {};

    for (int kt = 0; kt < nk; kt++) {
        int cur = kt & 1;
        if (kt + 1 < nk) { ldA(cur ^ 1, (kt + 1) * BK); ldB(cur ^ 1, (kt + 1) * BK); }
        asm volatile("cp.async.commit_group;\n");
        asm volatile("cp.async.wait_group 1;\n");
        __syncthreads();

        const __nv_bfloat16* sa = smA[cur];
        const __nv_bfloat16* sb = smB[cur];
#pragma unroll
        for (int kk = 0; kk < BK; kk += 16) {
            uint32_t af[MM][4];
            uint32_t bfr[MN][2];
#pragma unroll
            for (int mi = 0; mi < MM; mi++) {
                uint32_t addr = (uint32_t)__cvta_generic_to_shared(
                    &sa[(wm * WM + mi * 16 + (lane & 15)) * LDSB + kk + ((lane >> 4) << 3)]);
                asm volatile("ldmatrix.sync.aligned.m8n8.x4.shared.b16 {%0,%1,%2,%3}, [%4];\n"
                             : "=r"(af[mi][0]), "=r"(af[mi][1]), "=r"(af[mi][2]), "=r"(af[mi][3])
                             : "r"(addr));
            }
#pragma unroll
            for (int nj = 0; nj < MN / 2; nj++) {
                uint32_t r0, r1, r2, r3;
                uint32_t addr = (uint32_t)__cvta_generic_to_shared(
                    &sb[(wn * WN + nj * 16 + (lane & 15)) * LDSB + kk + ((lane >> 4) << 3)]);
                asm volatile("ldmatrix.sync.aligned.m8n8.x4.shared.b16 {%0,%1,%2,%3}, [%4];\n"
                             : "=r"(r0), "=r"(r1), "=r"(r2), "=r"(r3)
                             : "r"(addr));
                bfr[2 * nj][0] = r0; bfr[2 * nj + 1][0] = r1;
                bfr[2 * nj][1] = r2; bfr[2 * nj + 1][1] = r3;
            }
#pragma unroll
            for (int mi = 0; mi < MM; mi++)
#pragma unroll
                for (int ni = 0; ni < MN; ni++) {
                    asm volatile(
                        "mma.sync.aligned.m16n8k16.row.col.f32.bf16.bf16.f32 "
                        "{%0,%1,%2,%3}, {%4,%5,%6,%7}, {%8,%9}, {%0,%1,%2,%3};\n"
                        : "+f"(acc[mi][ni][0]), "+f"(acc[mi][ni][1]),
                          "+f"(acc[mi][ni][2]), "+f"(acc[mi][ni][3])
                        : "r"(af[mi][0]), "r"(af[mi][1]), "r"(af[mi][2]), "r"(af[mi][3]),
                          "r"(bfr[ni][0]), "r"(bfr[ni][1]));
                }
        }
        __syncthreads();
    }

    // ---- epilogue ----
    const int rb = m0 + wm * WM;
    const int cb = n0 + wn * WN;
#pragma unroll
    for (int mi = 0; mi < MM; mi++)
#pragma unroll
        for (int ni = 0; ni < MN; ni++)
#pragma unroll
            for (int h = 0; h < 2; h++) {
                int row = rb + mi * 16 + (lane >> 2) + h * 8;
                int col = cb + ni * 8 + ((lane & 3) << 1);
                float v0 = acc[mi][ni][2 * h + 0] + bias[col];
                float v1 = acc[mi][ni][2 * h + 1] + bias[col + 1];
                if (EPI == 0) {
                    __nv_bfloat162 t;
                    t.x = __float2bfloat16(v0); t.y = __float2bfloat16(v1);
                    *reinterpret_cast<__nv_bfloat162*>(outb + (long)row * N + col) = t;
                } else if (EPI == 1) {
                    float g0 = 0.5f * v0 * (1.f + erff(v0 * 0.70710678118654752f));
                    float g1 = 0.5f * v1 * (1.f + erff(v1 * 0.70710678118654752f));
                    __nv_bfloat162 t;
                    t.x = __float2bfloat16(g0); t.y = __float2bfloat16(g1);
                    *reinterpret_cast<__nv_bfloat162*>(outb + (long)row * N + col) = t;
                } else if (EPI == 2) {
                    // fold: row = b*1024 + r0*32 + r1 ; col = (p0*8+p1)*256 + c
                    int b  = row >> 10;
                    int l  = row & 1023;
                    int r0 = l >> 5, r1 = l & 31;
                    int p  = col >> 8;
                    int c  = col & 255;
                    int p0 = p >> 3, p1 = p & 7;
                    int hh = (r0 << 3) | p0;
                    int ww = (r1 << 3) | p1;
                    long dst = ((((long)b * 256 + hh) * 256 + ww) * 256) + c;
                    outf[dst]     = res[dst]     + v0;
                    outf[dst + 1] = res[dst + 1] + v1;
                } else {
                    long idx = (long)row * N + col;
                    outf[idx]     = res[idx]     + v0;
                    outf[idx + 1] = res[idx + 1] + v1;
                }
            }
}

// ---------------- flash attention with relative position bias ----------------
// grid: (B*NH=16, L/128=8), block: 128. Thread t owns query lq = qt*128 + t.
__global__ void __launch_bounds__(128) attn_kernel(
    const __nv_bfloat16* __restrict__ qkv,   // (2048, 768) [3, NH, DH] cols
    const float* __restrict__ rpe,           // (3969, 8)
    __nv_bfloat16* __restrict__ o)           // (2048, 256)
{
    const int bh = blockIdx.x;
    const int b  = bh >> 3;
    const int nh = bh & 7;
    const int t  = threadIdx.x;
    const int lq = blockIdx.y * 128 + t;
    const long rown = (long)b * 1024 + lq;

    float q[32];
    {
        const __nv_bfloat16* qp = qkv + rown * 768 + nh * 32;
#pragma unroll
        for (int d = 0; d < 32; d++)
            q[d] = __bfloat162float(qp[d]) * 0.1767766952966369f;  // 1/sqrt(32)
    }

    __shared__ __nv_bfloat16 sk[128][32];
    __shared__ __nv_bfloat16 sv[128][32];

    float m = -1e30f, lsum = 0.f;
    float accv[32] = {};
    const int i0 = lq >> 5, i1 = lq & 31;

    for (int kt = 0; kt < 8; kt++) {
        __syncthreads();
        // load 128 K rows and 128 V rows (each 32 bf16) with 16B vectors
#pragma unroll
        for (int it = 0; it < 4; it++) {
            int idx = t + it * 128;               // 0..511
            int r = idx >> 2, cc = (idx & 3) << 3;
            long krow = (long)b * 1024 + kt * 128 + r;
            *reinterpret_cast<uint4*>(&sk[r][cc]) =
                *reinterpret_cast<const uint4*>(qkv + krow * 768 + 256 + nh * 32 + cc);
            *reinterpret_cast<uint4*>(&sv[r][cc]) =
                *reinterpret_cast<const uint4*>(qkv + krow * 768 + 512 + nh * 32 + cc);
        }
        __syncthreads();

#pragma unroll 1
        for (int jc = 0; jc < 128; jc += 16) {
            float s[16];
            float cmax = -1e30f;
#pragma unroll
            for (int jj = 0; jj < 16; jj++) {
                int j = jc + jj;
                float d0 = 0.f;
#pragma unroll
                for (int d = 0; d < 32; d += 2) {
                    __nv_bfloat162 k2 = *reinterpret_cast<const __nv_bfloat162*>(&sk[j][d]);
                    d0 += q[d] * __low2float(k2) + q[d + 1] * __high2float(k2);
                }
                int kl = kt * 128 + j;
                int j0 = kl >> 5, j1 = kl & 31;
                int ridx = (i0 - j0 + 31) * 63 + (i1 - j1 + 31);
                d0 += __ldg(&rpe[ridx * 8 + nh]);
                s[jj] = d0;
                cmax = fmaxf(cmax, d0);
            }
            float mnew = fmaxf(m, cmax);
            float sc = __expf(m - mnew);
            lsum *= sc;
#pragma unroll
            for (int d = 0; d < 32; d++) accv[d] *= sc;
#pragma unroll
            for (int jj = 0; jj < 16; jj++) {
                float p = __expf(s[jj] - mnew);
                lsum += p;
                int j = jc + jj;
#pragma unroll
                for (int d = 0; d < 32; d += 2) {
                    __nv_bfloat162 v2 = *reinterpret_cast<const __nv_bfloat162*>(&sv[j][d]);
                    accv[d]     += p * __low2float(v2);
                    accv[d + 1] += p * __high2float(v2);
                }
            }
            m = mnew;
        }
    }

    float inv = 1.f / lsum;
    __nv_bfloat16* op = o + rown * 256 + nh * 32;
#pragma unroll
    for (int d = 0; d < 32; d += 2) {
        __nv_bfloat162 tt;
        tt.x = __float2bfloat16(accv[d] * inv);
        tt.y = __float2bfloat16(accv[d + 1] * inv);
        *reinterpret_cast<__nv_bfloat162*>(&op[d]) = tt;
    }
}

// ----------------------------------------------------------------------------
extern "C" void kernel_launch(void* const* d_in, const int* in_sizes, int n_in,
                              void* d_out, int out_size) {
    const float* x      = (const float*)d_in[0];
    const float* ln1_g  = (const float*)d_in[1];
    const float* ln1_b  = (const float*)d_in[2];
    const float* ln2_g  = (const float*)d_in[3];
    const float* ln2_b  = (const float*)d_in[4];
    const float* rpe    = (const float*)d_in[5];
    const float* w_down = (const float*)d_in[6];
    const float* b_down = (const float*)d_in[7];
    const float* w_up   = (const float*)d_in[8];
    const float* b_up   = (const float*)d_in[9];
    const float* w_qkv  = (const float*)d_in[10];
    const float* b_qkv  = (const float*)d_in[11];
    const float* w_proj = (const float*)d_in[12];
    const float* b_proj = (const float*)d_in[13];
    const float* w_fc1  = (const float*)d_in[14];
    const float* b_fc1  = (const float*)d_in[15];
    const float* w_fc2  = (const float*)d_in[16];
    const float* b_fc2  = (const float*)d_in[17];
    float* out = (float*)d_out;

    void *p_yhd, *p_y1, *p_qkv, *p_oattn, *p_oproj, *p_x2, *p_ln2, *p_h1;
    void *p_wd, *p_wu, *p_wq, *p_wp, *p_w1, *p_w2;
    cudaGetSymbolAddress(&p_yhd,   g_yhd);
    cudaGetSymbolAddress(&p_y1,    g_y1);
    cudaGetSymbolAddress(&p_qkv,   g_qkv);
    cudaGetSymbolAddress(&p_oattn, g_oattn);
    cudaGetSymbolAddress(&p_oproj, g_oproj);
    cudaGetSymbolAddress(&p_x2,    g_x2);
    cudaGetSymbolAddress(&p_ln2,   g_ln2);
    cudaGetSymbolAddress(&p_h1,    g_h1);
    cudaGetSymbolAddress(&p_wd,    g_wdown);
    cudaGetSymbolAddress(&p_wu,    g_wup);
    cudaGetSymbolAddress(&p_wq,    g_wqkv);
    cudaGetSymbolAddress(&p_wp,    g_wproj);
    cudaGetSymbolAddress(&p_w1,    g_wfc1);
    cudaGetSymbolAddress(&p_w2,    g_wfc2);

    auto cvt = [&](const float* src, void* dst, int n) {
        cvt_bf16_kernel<<<(n + 255) / 256, 256>>>(src, (__nv_bfloat16*)dst, n);
    };
    cvt(w_down, p_wd, 256 * 16384);
    cvt(w_up,   p_wu, 16384 * 256);
    cvt(w_qkv,  p_wq, 768 * 256);
    cvt(w_proj, p_wp, 256 * 256);
    cvt(w_fc1,  p_w1, 1024 * 256);
    cvt(w_fc2,  p_w2, 256 * 1024);

    // LN1 fused with unfold permutation
    ln_kernel<true><<<131072 / 8, 256>>>(x, ln1_g, ln1_b, (__nv_bfloat16*)p_yhd);

    // down-proj: (2048, 256) = (2048,16384) @ (256,16384)^T + b_down  -> bf16
    gemm_nt<64, 64, 2, 2, 0><<<dim3(256 / 64, 2048 / 64), 128>>>(
        (const __nv_bfloat16*)p_yhd, (const __nv_bfloat16*)p_wd,
        2048, 256, 16384, b_down, (__nv_bfloat16*)p_y1, nullptr, nullptr);

    // qkv: (2048, 768) = (2048,256) @ (768,256)^T + b_qkv -> bf16
    gemm_nt<64, 64, 2, 2, 0><<<dim3(768 / 64, 2048 / 64), 128>>>(
        (const __nv_bfloat16*)p_y1, (const __nv_bfloat16*)p_wq,
        2048, 768, 256, b_qkv, (__nv_bfloat16*)p_qkv, nullptr, nullptr);

    // attention with relative position bias
    attn_kernel<<<dim3(16, 8), 128>>>((const __nv_bfloat16*)p_qkv, rpe,
                                      (__nv_bfloat16*)p_oattn);

    // proj: (2048,256) = (2048,256) @ (256,256)^T + b_proj -> bf16
    gemm_nt<64, 64, 2, 2, 0><<<dim3(256 / 64, 2048 / 64), 128>>>(
        (const __nv_bfloat16*)p_oattn, (const __nv_bfloat16*)p_wp,
        2048, 256, 256, b_proj, (__nv_bfloat16*)p_oproj, nullptr, nullptr);

    // up-proj + fold + residual: x2 = x + fold((2048,256)@(16384,256)^T + b_up)
    gemm_nt<128, 128, 2, 4, 2><<<dim3(16384 / 128, 2048 / 128), 256>>>(
        (const __nv_bfloat16*)p_oproj, (const __nv_bfloat16*)p_wu,
        2048, 16384, 256, b_up, nullptr, (float*)p_x2, x);

    // LN2
    ln_kernel<false><<<131072 / 8, 256>>>((const float*)p_x2, ln2_g, ln2_b,
                                          (__nv_bfloat16*)p_ln2);

    // fc1 + exact GELU: (131072,1024) = (131072,256) @ (1024,256)^T -> bf16
    gemm_nt<128, 128, 2, 4, 1><<<dim3(1024 / 128, 131072 / 128), 256>>>(
        (const __nv_bfloat16*)p_ln2, (const __nv_bfloat16*)p_w1,
        131072, 1024, 256, b_fc1, (__nv_bfloat16*)p_h1, nullptr, nullptr);

    // fc2 + residual: out = x2 + (131072,1024) @ (256,1024)^T + b_fc2  (fp32)
    gemm_nt<128, 128, 2, 4, 3><<<dim3(256 / 128, 131072 / 128), 256>>>(
        (const __nv_bfloat16*)p_h1, (const __nv_bfloat16*)p_w2,
        131072, 256, 1024, b_fc2, nullptr, out, (const float*)p_x2);

    (void)in_sizes; (void)n_in; (void)out_size;
}

// round 4
// speedup vs baseline: 1.3568x; 1.3568x over previous
#include <cuda_runtime.h>
#include <cuda_bf16.h>
#include <math.h>
#include <stdint.h>

#define DINLINE __device__ __forceinline__
typedef unsigned long long u64t;

// ---------------- scratch (device globals; no allocation allowed) -----------
__device__ __nv_bfloat16 g_yhd  [2048L * 16384];
__device__ __nv_bfloat16 g_y1   [2048L * 256];
__device__ __nv_bfloat16 g_qkv  [2048L * 768];
__device__ __nv_bfloat16 g_oattn[2048L * 256];
__device__ __nv_bfloat16 g_oproj[2048L * 256];
__device__ float         g_x2   [131072L * 256];
__device__ __nv_bfloat16 g_ln2  [131072L * 256];
__device__ __nv_bfloat16 g_h1   [131072L * 1024];
__device__ float         g_part [8L * 2048 * 256];
__device__ __nv_bfloat16 g_wdown[256L * 16384];
__device__ __nv_bfloat16 g_wup  [16384L * 256];
__device__ __nv_bfloat16 g_wqkv [768L * 256];
__device__ __nv_bfloat16 g_wproj[256L * 256];
__device__ __nv_bfloat16 g_wfc1 [1024L * 256];
__device__ __nv_bfloat16 g_wfc2 [256L * 1024];

// ---------------- packed f32x2 helpers ---------------------------------------
DINLINE u64t pack2(float lo, float hi) {
    u64t r; asm("mov.b64 %0, {%1, %2};" : "=l"(r) : "f"(lo), "f"(hi)); return r;
}
DINLINE void unpack2(u64t v, float& lo, float& hi) {
    asm("mov.b64 {%0, %1}, %2;" : "=f"(lo), "=f"(hi) : "l"(v));
}
DINLINE u64t fma2(u64t a, u64t b, u64t c) {
    u64t d; asm("fma.rn.f32x2 %0, %1, %2, %3;" : "=l"(d) : "l"(a), "l"(b), "l"(c)); return d;
}
DINLINE u64t mul2(u64t a, u64t b) {
    u64t d; asm("mul.rn.f32x2 %0, %1, %2;" : "=l"(d) : "l"(a), "l"(b)); return d;
}

// ---------------- fp32 -> bf16 convert ---------------------------------------
__global__ void cvt_bf16_kernel(const float* __restrict__ in,
                                __nv_bfloat16* __restrict__ out, int n) {
    int i = blockIdx.x * 256 + threadIdx.x;
    if (i < n) out[i] = __float2bfloat16(in[i]);
}

// ---------------- LayerNorm (optionally fused with unfold permutation) -------
template <bool PERM>
__global__ void ln_kernel(const float* __restrict__ in,
                          const float* __restrict__ gamma,
                          const float* __restrict__ beta,
                          __nv_bfloat16* __restrict__ out) {
    int row  = blockIdx.x * 8 + (threadIdx.x >> 5);
    int lane = threadIdx.x & 31;
    const float* p = in + (long)row * 256;

    float v[8];
    float s = 0.f;
#pragma unroll
    for (int i = 0; i < 8; i++) { v[i] = p[lane + i * 32]; s += v[i]; }
#pragma unroll
    for (int o = 16; o > 0; o >>= 1) s += __shfl_xor_sync(0xffffffffu, s, o);
    float mean = s * (1.f / 256.f);
    float q = 0.f;
#pragma unroll
    for (int i = 0; i < 8; i++) { float d = v[i] - mean; q += d * d; }
#pragma unroll
    for (int o = 16; o > 0; o >>= 1) q += __shfl_xor_sync(0xffffffffu, q, o);
    float rstd = rsqrtf(q * (1.f / 256.f) + 1e-5f);

    long obase;
    if (PERM) {
        int b  = row >> 16;
        int hh = (row >> 8) & 255;
        int ww = row & 255;
        int r0 = hh >> 3, p0 = hh & 7;
        int r1 = ww >> 3, p1 = ww & 7;
        long n = (long)b * 1024 + r0 * 32 + r1;
        obase = n * 16384 + (long)(p0 * 8 + p1) * 256;
    } else {
        obase = (long)row * 256;
    }
#pragma unroll
    for (int i = 0; i < 8; i++) {
        int c = lane + i * 32;
        float y = (v[i] - mean) * rstd * gamma[c] + beta[c];
        out[obase + c] = __float2bfloat16(y);
    }
}

// ---------------- NT bf16 GEMM (mma.sync m16n8k16, fp32 accum) ----------------
// C[M,N] = A[M,K] bf16 row-major @ B[N,K]^T bf16 row-major (+ epilogue)
// CTA tile 128x128, BK=64, 2-stage cp.async, 8 warps (2x4), warp tile 64x32.
// EPI: 0 bias->bf16 | 1 bias+GELU->bf16 | 2 bias+fold+res->f32 |
//      3 bias+res->f32 | 4 raw f32 partial (split-K over blockIdx.z)
template <int EPI>
__global__ void __launch_bounds__(256, 2)
gemm_nt(const __nv_bfloat16* __restrict__ A,
        const __nv_bfloat16* __restrict__ B,
        int M, int N, long K, int k_len,
        const float* __restrict__ bias,
        __nv_bfloat16* __restrict__ outb,
        float* __restrict__ outf,
        const float* __restrict__ res,
        float* __restrict__ part) {
    constexpr int BM = 128, BN = 128, BK = 64;
    constexpr int LDSB = BK + 8;                 // 72 bf16 = 144B (16B-aligned rows)
    constexpr int STG_ELEMS = BM * LDSB;         // 9216 per matrix

    extern __shared__ __nv_bfloat16 sm[];        // [2 stages][A(9216) | B(9216)]

    const int tid  = threadIdx.x;
    const int lane = tid & 31;
    const int wid  = tid >> 5;
    const int wm   = wid >> 2;                   // 0..1
    const int wn   = wid & 3;                    // 0..3
    const int m0   = blockIdx.y << 7;
    const int n0   = blockIdx.x << 7;
    const long koff = (long)blockIdx.z * k_len;
    const int nk   = k_len >> 6;

    auto ldAB = [&](int st, long kc) {
        __nv_bfloat16* sa = sm + st * (2 * STG_ELEMS);
        __nv_bfloat16* sb = sa + STG_ELEMS;
#pragma unroll
        for (int it = 0; it < 4; ++it) {
            int idx = tid + (it << 8);           // 0..1023
            int r   = idx >> 3;                  // 0..127
            int c8  = (idx & 7) << 3;            // 0..56
            const __nv_bfloat16* srcA = A + (long)(m0 + r) * K + kc + c8;
            uint32_t da = (uint32_t)__cvta_generic_to_shared(&sa[r * LDSB + c8]);
            asm volatile("cp.async.cg.shared.global [%0], [%1], 16;" ::"r"(da), "l"(srcA));
            const __nv_bfloat16* srcB = B + (long)(n0 + r) * K + kc + c8;
            uint32_t db = (uint32_t)__cvta_generic_to_shared(&sb[r * LDSB + c8]);
            asm volatile("cp.async.cg.shared.global [%0], [%1], 16;" ::"r"(db), "l"(srcB));
        }
    };

    ldAB(0, koff);
    asm volatile("cp.async.commit_group;");

    float acc[4][4][4] = {};

    for (int kt = 0; kt < nk; ++kt) {
        int cur = kt & 1;
        if (kt + 1 < nk) ldAB(cur ^ 1, koff + ((long)(kt + 1) << 6));
        asm volatile("cp.async.commit_group;");
        asm volatile("cp.async.wait_group 1;");
        __syncthreads();

        const __nv_bfloat16* sa = sm + cur * (2 * STG_ELEMS);
        const __nv_bfloat16* sb = sa + STG_ELEMS;
#pragma unroll
        for (int kk = 0; kk < BK; kk += 16) {
            uint32_t af[4][4];
            uint32_t bfr[4][2];
#pragma unroll
            for (int mi = 0; mi < 4; mi++) {
                uint32_t addr = (uint32_t)__cvta_generic_to_shared(
                    &sa[(wm * 64 + mi * 16 + (lane & 15)) * LDSB + kk + ((lane >> 4) << 3)]);
                asm volatile("ldmatrix.sync.aligned.m8n8.x4.shared.b16 {%0,%1,%2,%3}, [%4];"
                             : "=r"(af[mi][0]), "=r"(af[mi][1]), "=r"(af[mi][2]), "=r"(af[mi][3])
                             : "r"(addr));
            }
#pragma unroll
            for (int nj = 0; nj < 2; nj++) {
                uint32_t r0, r1, r2, r3;
                uint32_t addr = (uint32_t)__cvta_generic_to_shared(
                    &sb[(wn * 32 + nj * 16 + (lane & 15)) * LDSB + kk + ((lane >> 4) << 3)]);
                asm volatile("ldmatrix.sync.aligned.m8n8.x4.shared.b16 {%0,%1,%2,%3}, [%4];"
                             : "=r"(r0), "=r"(r1), "=r"(r2), "=r"(r3)
                             : "r"(addr));
                bfr[2 * nj][0] = r0; bfr[2 * nj + 1][0] = r1;
                bfr[2 * nj][1] = r2; bfr[2 * nj + 1][1] = r3;
            }
#pragma unroll
            for (int mi = 0; mi < 4; mi++)
#pragma unroll
                for (int ni = 0; ni < 4; ni++) {
                    asm volatile(
                        "mma.sync.aligned.m16n8k16.row.col.f32.bf16.bf16.f32 "
                        "{%0,%1,%2,%3}, {%4,%5,%6,%7}, {%8,%9}, {%0,%1,%2,%3};"
                        : "+f"(acc[mi][ni][0]), "+f"(acc[mi][ni][1]),
                          "+f"(acc[mi][ni][2]), "+f"(acc[mi][ni][3])
                        : "r"(af[mi][0]), "r"(af[mi][1]), "r"(af[mi][2]), "r"(af[mi][3]),
                          "r"(bfr[ni][0]), "r"(bfr[ni][1]));
                }
        }
        __syncthreads();
    }

    // ---- epilogue ----
    const int rb = m0 + wm * 64;
    const int cb = n0 + wn * 32;
#pragma unroll
    for (int mi = 0; mi < 4; mi++)
#pragma unroll
        for (int ni = 0; ni < 4; ni++)
#pragma unroll
            for (int h = 0; h < 2; h++) {
                int row = rb + mi * 16 + (lane >> 2) + h * 8;
                int col = cb + ni * 8 + ((lane & 3) << 1);
                float v0 = acc[mi][ni][2 * h + 0];
                float v1 = acc[mi][ni][2 * h + 1];
                if (EPI != 4) { v0 += bias[col]; v1 += bias[col + 1]; }
                if (EPI == 0) {
                    __nv_bfloat162 t;
                    t.x = __float2bfloat16(v0); t.y = __float2bfloat16(v1);
                    *reinterpret_cast<__nv_bfloat162*>(outb + (long)row * N + col) = t;
                } else if (EPI == 1) {
                    float g0 = 0.5f * v0 * (1.f + erff(v0 * 0.70710678118654752f));
                    float g1 = 0.5f * v1 * (1.f + erff(v1 * 0.70710678118654752f));
                    __nv_bfloat162 t;
                    t.x = __float2bfloat16(g0); t.y = __float2bfloat16(g1);
                    *reinterpret_cast<__nv_bfloat162*>(outb + (long)row * N + col) = t;
                } else if (EPI == 2) {
                    int b  = row >> 10;
                    int l  = row & 1023;
                    int r0 = l >> 5, r1 = l & 31;
                    int p  = col >> 8;
                    int c  = col & 255;
                    int p0 = p >> 3, p1 = p & 7;
                    int hh = (r0 << 3) | p0;
                    int ww = (r1 << 3) | p1;
                    long dst = ((((long)b * 256 + hh) * 256 + ww) * 256) + c;
                    outf[dst]     = res[dst]     + v0;
                    outf[dst + 1] = res[dst + 1] + v1;
                } else if (EPI == 3) {
                    long idx = (long)row * N + col;
                    outf[idx]     = res[idx]     + v0;
                    outf[idx + 1] = res[idx + 1] + v1;
                } else {  // EPI 4: split-K partial
                    long idx = ((long)blockIdx.z * M + row) * N + col;
                    part[idx]     = v0;
                    part[idx + 1] = v1;
                }
            }
}

// ---------------- down-proj split-K reduce ------------------------------------
__global__ void reduce_down(const float* __restrict__ part,
                            const float* __restrict__ bias,
                            __nv_bfloat16* __restrict__ out) {
    int i = blockIdx.x * 256 + threadIdx.x;     // over 2048*256
    float s = bias[i & 255];
#pragma unroll
    for (int z = 0; z < 8; ++z) s += part[(long)z * 524288 + i];
    out[i] = __float2bfloat16(s);
}

// ---------------- flash attention (packed f32x2) ------------------------------
__global__ void __launch_bounds__(128) attn_kernel(
    const __nv_bfloat16* __restrict__ qkv,   // (2048, 768) [q|k|v] x (NH, DH)
    const float* __restrict__ rpe,           // (3969, 8)
    __nv_bfloat16* __restrict__ o)           // (2048, 256)
{
    const int bh = blockIdx.x;
    const int b  = bh >> 3;
    const int nh = bh & 7;
    const int t  = threadIdx.x;
    const int lq = blockIdx.y * 128 + t;
    const long rown = (long)b * 1024 + lq;

    u64t q2[16];
    {
        const __nv_bfloat16* qp = qkv + rown * 768 + nh * 32;
#pragma unroll
        for (int d = 0; d < 16; d++) {
            float lo = __bfloat162float(qp[2 * d])     * 0.1767766952966369f;
            float hi = __bfloat162float(qp[2 * d + 1]) * 0.1767766952966369f;
            q2[d] = pack2(lo, hi);
        }
    }

    __shared__ float sk[128][32];
    __shared__ float sv[128][32];

    float m = -1e30f, lsum = 0.f;
    u64t acc2[16];
#pragma unroll
    for (int d = 0; d < 16; d++) acc2[d] = 0ull;
    const int i0 = lq >> 5, i1 = lq & 31;

    for (int kt = 0; kt < 8; ++kt) {
        __syncthreads();
#pragma unroll
        for (int it = 0; it < 16; ++it) {
            int idx = t + it * 128;
            int r = idx >> 4, d2 = idx & 15;
            long krow = (long)b * 1024 + kt * 128 + r;
            __nv_bfloat162 kk = *(const __nv_bfloat162*)(qkv + krow * 768 + 256 + nh * 32 + 2 * d2);
            sk[r][2 * d2]     = __low2float(kk);
            sk[r][2 * d2 + 1] = __high2float(kk);
            __nv_bfloat162 vv = *(const __nv_bfloat162*)(qkv + krow * 768 + 512 + nh * 32 + 2 * d2);
            sv[r][2 * d2]     = __low2float(vv);
            sv[r][2 * d2 + 1] = __high2float(vv);
        }
        __syncthreads();

#pragma unroll 1
        for (int jc = 0; jc < 128; jc += 16) {
            float s[16];
            float cmax = -1e30f;
#pragma unroll
            for (int jj = 0; jj < 16; ++jj) {
                const u64t* kr = (const u64t*)sk[jc + jj];
                u64t s2 = 0ull;
#pragma unroll
                for (int d = 0; d < 16; ++d) s2 = fma2(q2[d], kr[d], s2);
                float lo, hi; unpack2(s2, lo, hi);
                int kl = kt * 128 + jc + jj;
                int j0 = kl >> 5, j1 = kl & 31;
                float sc = lo + hi +
                    __ldg(&rpe[((i0 - j0 + 31) * 63 + (i1 - j1 + 31)) * 8 + nh]);
                s[jj] = sc;
                cmax = fmaxf(cmax, sc);
            }
            float mnew  = fmaxf(m, cmax);
            float scale = __expf(m - mnew);
            lsum *= scale;
            u64t sc2 = pack2(scale, scale);
#pragma unroll
            for (int d = 0; d < 16; ++d) acc2[d] = mul2(acc2[d], sc2);
#pragma unroll
            for (int jj = 0; jj < 16; ++jj) {
                float p = __expf(s[jj] - mnew);
                lsum += p;
                u64t p2 = pack2(p, p);
                const u64t* vr = (const u64t*)sv[jc + jj];
#pragma unroll
                for (int d = 0; d < 16; ++d) acc2[d] = fma2(p2, vr[d], acc2[d]);
            }
            m = mnew;
        }
    }

    float inv = 1.f / lsum;
    __nv_bfloat16* op = o + rown * 256 + nh * 32;
#pragma unroll
    for (int d = 0; d < 16; ++d) {
        float lo, hi; unpack2(acc2[d], lo, hi);
        __nv_bfloat162 tt;
        tt.x = __float2bfloat16(lo * inv);
        tt.y = __float2bfloat16(hi * inv);
        *(__nv_bfloat162*)(op + 2 * d) = tt;
    }
}

// ----------------------------------------------------------------------------
extern "C" void kernel_launch(void* const* d_in, const int* in_sizes, int n_in,
                              void* d_out, int out_size) {
    const float* x      = (const float*)d_in[0];
    const float* ln1_g  = (const float*)d_in[1];
    const float* ln1_b  = (const float*)d_in[2];
    const float* ln2_g  = (const float*)d_in[3];
    const float* ln2_b  = (const float*)d_in[4];
    const float* rpe    = (const float*)d_in[5];
    const float* w_down = (const float*)d_in[6];
    const float* b_down = (const float*)d_in[7];
    const float* w_up   = (const float*)d_in[8];
    const float* b_up   = (const float*)d_in[9];
    const float* w_qkv  = (const float*)d_in[10];
    const float* b_qkv  = (const float*)d_in[11];
    const float* w_proj = (const float*)d_in[12];
    const float* b_proj = (const float*)d_in[13];
    const float* w_fc1  = (const float*)d_in[14];
    const float* b_fc1  = (const float*)d_in[15];
    const float* w_fc2  = (const float*)d_in[16];
    const float* b_fc2  = (const float*)d_in[17];
    float* out = (float*)d_out;

    void *p_yhd, *p_y1, *p_qkv, *p_oattn, *p_oproj, *p_x2, *p_ln2, *p_h1, *p_part;
    void *p_wd, *p_wu, *p_wq, *p_wp, *p_w1, *p_w2;
    cudaGetSymbolAddress(&p_yhd,   g_yhd);
    cudaGetSymbolAddress(&p_y1,    g_y1);
    cudaGetSymbolAddress(&p_qkv,   g_qkv);
    cudaGetSymbolAddress(&p_oattn, g_oattn);
    cudaGetSymbolAddress(&p_oproj, g_oproj);
    cudaGetSymbolAddress(&p_x2,    g_x2);
    cudaGetSymbolAddress(&p_ln2,   g_ln2);
    cudaGetSymbolAddress(&p_h1,    g_h1);
    cudaGetSymbolAddress(&p_part,  g_part);
    cudaGetSymbolAddress(&p_wd,    g_wdown);
    cudaGetSymbolAddress(&p_wu,    g_wup);
    cudaGetSymbolAddress(&p_wq,    g_wqkv);
    cudaGetSymbolAddress(&p_wp,    g_wproj);
    cudaGetSymbolAddress(&p_w1,    g_wfc1);
    cudaGetSymbolAddress(&p_w2,    g_wfc2);

    const int SMEM_GEMM = 2 * 2 * 128 * 72 * 2;   // 73728 B
    cudaFuncSetAttribute(gemm_nt<0>, cudaFuncAttributeMaxDynamicSharedMemorySize, SMEM_GEMM);
    cudaFuncSetAttribute(gemm_nt<1>, cudaFuncAttributeMaxDynamicSharedMemorySize, SMEM_GEMM);
    cudaFuncSetAttribute(gemm_nt<2>, cudaFuncAttributeMaxDynamicSharedMemorySize, SMEM_GEMM);
    cudaFuncSetAttribute(gemm_nt<3>, cudaFuncAttributeMaxDynamicSharedMemorySize, SMEM_GEMM);
    cudaFuncSetAttribute(gemm_nt<4>, cudaFuncAttributeMaxDynamicSharedMemorySize, SMEM_GEMM);

    auto cvt = [&](const float* src, void* dst, int n) {
        cvt_bf16_kernel<<<(n + 255) / 256, 256>>>(src, (__nv_bfloat16*)dst, n);
    };
    cvt(w_down, p_wd, 256 * 16384);
    cvt(w_up,   p_wu, 16384 * 256);
    cvt(w_qkv,  p_wq, 768 * 256);
    cvt(w_proj, p_wp, 256 * 256);
    cvt(w_fc1,  p_w1, 1024 * 256);
    cvt(w_fc2,  p_w2, 256 * 1024);

    // LN1 fused with unfold permutation
    ln_kernel<true><<<131072 / 8, 256>>>(x, ln1_g, ln1_b, (__nv_bfloat16*)p_yhd);

    // down-proj split-K=8 -> partials, then reduce(+bias) -> bf16
    gemm_nt<4><<<dim3(2, 16, 8), 256, SMEM_GEMM>>>(
        (const __nv_bfloat16*)p_yhd, (const __nv_bfloat16*)p_wd,
        2048, 256, 16384L, 2048, nullptr, nullptr, nullptr, nullptr, (float*)p_part);
    reduce_down<<<524288 / 256, 256>>>((const float*)p_part, b_down, (__nv_bfloat16*)p_y1);

    // qkv
    gemm_nt<0><<<dim3(6, 16), 256, SMEM_GEMM>>>(
        (const __nv_bfloat16*)p_y1, (const __nv_bfloat16*)p_wq,
        2048, 768, 256L, 256, b_qkv, (__nv_bfloat16*)p_qkv, nullptr, nullptr, nullptr);

    // attention
    attn_kernel<<<dim3(16, 8), 128>>>((const __nv_bfloat16*)p_qkv, rpe,
                                      (__nv_bfloat16*)p_oattn);

    // proj
    gemm_nt<0><<<dim3(2, 16), 256, SMEM_GEMM>>>(
        (const __nv_bfloat16*)p_oattn, (const __nv_bfloat16*)p_wp,
        2048, 256, 256L, 256, b_proj, (__nv_bfloat16*)p_oproj, nullptr, nullptr, nullptr);

    // up-proj + fold + residual: x2 = x + fold(...)
    gemm_nt<2><<<dim3(128, 16), 256, SMEM_GEMM>>>(
        (const __nv_bfloat16*)p_oproj, (const __nv_bfloat16*)p_wu,
        2048, 16384, 256L, 256, b_up, nullptr, (float*)p_x2, x, nullptr);

    // LN2
    ln_kernel<false><<<131072 / 8, 256>>>((const float*)p_x2, ln2_g, ln2_b,
                                          (__nv_bfloat16*)p_ln2);

    // fc1 + exact GELU
    gemm_nt<1><<<dim3(8, 1024), 256, SMEM_GEMM>>>(
        (const __nv_bfloat16*)p_ln2, (const __nv_bfloat16*)p_w1,
        131072, 1024, 256L, 256, b_fc1, (__nv_bfloat16*)p_h1, nullptr, nullptr, nullptr);

    // fc2 + residual -> out (fp32)
    gemm_nt<3><<<dim3(2, 1024), 256, SMEM_GEMM>>>(
        (const __nv_bfloat16*)p_h1, (const __nv_bfloat16*)p_w2,
        131072, 256, 1024L, 1024, b_fc2, nullptr, out, (const float*)p_x2, nullptr);

    (void)in_sizes; (void)n_in; (void)out_size;
}